// round 11
// baseline (speedup 1.0000x reference)
#include <cuda_runtime.h>
#include <math.h>

// GCNNet: 2x GCNConv(+self loops, sym norm) -> mean pool -> 4-layer MLP
// N=50000 nodes, E=800000 edges, 64 graphs, fp32 throughout.
//
//  - A(XW) == (AX)W : aggregate both layers at 64 channels.
//  - k_build: ONE kernel builds the whole CSR (zero/detect -> convert+hist ->
//    scan -> apply/offsets -> fill) using software grid barriers.
//    __threadfence() (gpu scope) flushes L1 on sm_103a, giving cross-block
//    visibility after each barrier. Counters reset each call by k_poolmlp.
//  - gemm1 (no deps: dinv applied in agg0) overlaps k_build on a side stream.
//  - agg0 fuses layer-1 epilogue; fused2 = agg + GEMM2 + bias + relu +
//    BLOCK-GRANULAR mean-pool atomics (128/block fast path) -> h2 eliminated.
//  - poolmlp: tiny per-graph MLP on pooled sums.

#define MAXN 50000
#define MAXE 800000
#define NG 64
#define NB 196          // ceil(50000/256); k_build grid size

__device__ int      g_is64;
__device__ float    g_dinv[MAXN];
__device__ int      g_cnt[MAXN];
__device__ int      g_rowstart[MAXN + 1];
__device__ int      g_cursor[MAXN];
__device__ int      g_csr[MAXE];
__device__ int      g_src32[MAXE];
__device__ int      g_dst32[MAXE];
__device__ int      g_bsum[256];
__device__ unsigned g_bar[4];
__device__ float    g_hsA[MAXN * 64];
__device__ float    g_hsB[MAXN * 64];
__device__ int      g_off[NG + 1];
__device__ float    g_pool[NG * 128];

__device__ __forceinline__ int load_idx(const void* p, long long i) {
    return g_is64 ? (int)((const long long*)p)[i] : ((const int*)p)[i];
}

// Software grid barrier: release fence + atomic arrive, spin (L2 reads),
// then acquire fence (flushes L1 on sm_103a so remote writes are visible).
__device__ __forceinline__ void gridbar(int id, unsigned nb) {
    __syncthreads();
    if (threadIdx.x == 0) {
        __threadfence();
        atomicAdd(&g_bar[id], 1u);
        while (*(volatile unsigned*)&g_bar[id] < nb) __nanosleep(64);
    }
    __syncthreads();
    __threadfence();
}

// Side stream + events (host objects, created once at load; no device allocs).
namespace {
struct Aux {
    cudaStream_t s;
    cudaEvent_t fork, join;
    Aux() {
        cudaStreamCreateWithFlags(&s, cudaStreamNonBlocking);
        cudaEventCreateWithFlags(&fork, cudaEventDisableTiming);
        cudaEventCreateWithFlags(&join, cudaEventDisableTiming);
    }
};
Aux g_aux;
}

// ---------------------------------------------------------------------------
// Whole CSR build in one kernel. Grid MUST be NB blocks x 256 threads
// (co-resident: 196 blocks of 256thr fit trivially on 148 SMs).
__global__ __launch_bounds__(256) void k_build(const void* ei, const void* bt,
                                               int E, int N) {
    int t = threadIdx.x, b = blockIdx.x;
    int i = b * 256 + t;
    int total = NB * 256;

    // P0: zero histogram + pool accumulators, detect index dtype
    if (i < N) g_cnt[i] = 0;
    if (i < NG * 128) g_pool[i] = 0.f;
    if (b == 0 && t < 32) {
        unsigned m = __ballot_sync(0xffffffffu, ((const int*)ei)[2 * t + 1] != 0);
        if (t == 0) g_is64 = (m == 0u) ? 1 : 0;
    }
    gridbar(0, NB);

    // P1: convert indices to int32 + histogram of dst
    for (int e = i; e < E; e += total) {
        int d = load_idx(ei, (long long)E + e);
        int s = load_idx(ei, e);
        g_src32[e] = s;
        g_dst32[e] = d;
        atomicAdd(&g_cnt[d], 1);
    }
    gridbar(1, NB);

    // P2a: per-block sum of counts
    int c = (i < N) ? g_cnt[i] : 0;
    {
        int v = c;
#pragma unroll
        for (int o = 16; o; o >>= 1) v += __shfl_down_sync(0xffffffffu, v, o);
        __shared__ int ws[8];
        if ((t & 31) == 0) ws[t >> 5] = v;
        __syncthreads();
        if (t == 0) {
            int s = 0;
#pragma unroll
            for (int j = 0; j < 8; j++) s += ws[j];
            g_bsum[b] = s;
        }
    }
    gridbar(2, NB);

    // P2b: every block scans g_bsum redundantly, then intra-block scan
    {
        __shared__ int sb[256];
        __shared__ int wt[8];
        __shared__ int wo[8];
        sb[t] = (t < NB) ? g_bsum[t] : 0;
        __syncthreads();
        for (int o = 1; o < 256; o <<= 1) {
            int val = sb[t];
            int add = (t >= o) ? sb[t - o] : 0;
            __syncthreads();
            sb[t] = val + add;
            __syncthreads();
        }
        int blockoff = (b == 0) ? 0 : sb[b - 1];

        int lane = t & 31, w = t >> 5;
        int x = c;
#pragma unroll
        for (int o = 1; o < 32; o <<= 1) {
            int y = __shfl_up_sync(0xffffffffu, x, o);
            if (lane >= o) x += y;
        }
        if (lane == 31) wt[w] = x;
        __syncthreads();
        if (t < 8) {
            int s = 0;
            for (int j = 0; j < t; j++) s += wt[j];
            wo[t] = s;
        }
        __syncthreads();
        if (i < N) {
            int excl = x - c + wo[w] + blockoff;
            g_rowstart[i] = excl;
            g_cursor[i]   = excl;
            g_dinv[i]     = rsqrtf((float)(c + 1));  // +1 self loop

            int bb = load_idx(bt, i);
            int bp = (i == 0) ? -1 : load_idx(bt, i - 1);
            for (int g = bp + 1; g <= bb; g++) g_off[g] = i;
            if (i == N - 1) {
                for (int g = bb + 1; g <= NG; g++) g_off[g] = N;
            }
        }
        if (i == 0) g_rowstart[N] = E;
    }
    gridbar(3, NB);

    // P3: fill CSR (reads the int32 copies this thread wrote in P1)
    for (int e = i; e < E; e += total) {
        int d = g_dst32[e];
        int s = g_src32[e];
        int pos = atomicAdd(&g_cursor[d], 1);
        g_csr[pos] = s;
    }
}

// ---------------------------------------------------------------------------
// GEMM1: hsA[r][c] = (x[r] @ W1)[c]   (UNSCALED; dinv applied in agg0)
// 128 threads, 64x64 tile, 8x4 per thread, K halved. FMA-floor-bound.
__global__ __launch_bounds__(128) void k_gemm1(const float* __restrict__ x,
                                               const float* __restrict__ W1, int N) {
    __shared__ float xs[64 * 64];
    __shared__ float ws[64 * 64];
    int t = threadIdx.x;
    int row0 = blockIdx.x * 64;
    int rg = t >> 4, cg = t & 15;

    float a[8][4] = {};
    const float4* W14 = (const float4*)W1;
    const float4* x4  = (const float4*)x;
    float4* ws4 = (float4*)ws;
    float4* xs4 = (float4*)xs;

    for (int kh = 0; kh < 2; kh++) {
        __syncthreads();
        for (int i = t; i < 1024; i += 128) {
            int k = i >> 4, c4 = i & 15;
            ws4[i] = W14[(size_t)(kh * 64 + k) * 16 + c4];
        }
        for (int i = t; i < 1024; i += 128) {
            int r = i >> 4, kk = i & 15;
            int gr = row0 + r;
            xs4[r * 16 + kk] = (gr < N) ? x4[(size_t)gr * 32 + kh * 16 + kk]
                                        : make_float4(0.f, 0.f, 0.f, 0.f);
        }
        __syncthreads();
#pragma unroll
        for (int k = 0; k < 64; k += 4) {
            float4 xv[8];
#pragma unroll
            for (int i = 0; i < 8; i++)
                xv[i] = *(const float4*)&xs[(rg * 8 + i) * 64 + k];
#pragma unroll
            for (int kk = 0; kk < 4; kk++) {
                float4 w = *(const float4*)&ws[(k + kk) * 64 + cg * 4];
#pragma unroll
                for (int i = 0; i < 8; i++) {
                    float xvv = ((const float*)&xv[i])[kk];
                    a[i][0] += xvv * w.x; a[i][1] += xvv * w.y;
                    a[i][2] += xvv * w.z; a[i][3] += xvv * w.w;
                }
            }
        }
    }
#pragma unroll
    for (int i = 0; i < 8; i++) {
        int gr = row0 + rg * 8 + i;
        if (gr < N) {
            *(float4*)&g_hsA[(size_t)gr * 64 + cg * 4] =
                make_float4(a[i][0], a[i][1], a[i][2], a[i][3]);
        }
    }
}

// ---------------------------------------------------------------------------
// agg0: hsB = relu( (Σ hsA[src]*dinv[src] + hsA[i]*dinv[i]) * dinv[i] + b1 ) * dinv[i]
__global__ __launch_bounds__(256) void k_agg0(const float* __restrict__ b1, int N) {
    const float2* hs = (const float2*)g_hsA;
    int warp = (blockIdx.x * blockDim.x + threadIdx.x) >> 5;
    int lane = threadIdx.x & 31;
    if (warp >= N) return;

    int s = g_rowstart[warp];
    int e = g_rowstart[warp + 1];
    float d = g_dinv[warp];
    float2 acc = hs[(size_t)warp * 32 + lane];  // self loop
    acc.x *= d; acc.y *= d;
    int j = s;
    for (; j + 3 < e; j += 4) {
        int s0 = g_csr[j], s1 = g_csr[j + 1], s2 = g_csr[j + 2], s3 = g_csr[j + 3];
        float d0 = g_dinv[s0], d1 = g_dinv[s1], d2 = g_dinv[s2], d3 = g_dinv[s3];
        float2 v0 = hs[(size_t)s0 * 32 + lane];
        float2 v1 = hs[(size_t)s1 * 32 + lane];
        float2 v2 = hs[(size_t)s2 * 32 + lane];
        float2 v3 = hs[(size_t)s3 * 32 + lane];
        acc.x += v0.x * d0 + v1.x * d1 + v2.x * d2 + v3.x * d3;
        acc.y += v0.y * d0 + v1.y * d1 + v2.y * d2 + v3.y * d3;
    }
    for (; j < e; j++) {
        int s0 = g_csr[j];
        float d0 = g_dinv[s0];
        float2 v0 = hs[(size_t)s0 * 32 + lane];
        acc.x += v0.x * d0;
        acc.y += v0.y * d0;
    }
    float2 bb = __ldg(&((const float2*)b1)[lane]);
    float2 o;
    o.x = fmaxf(acc.x * d + bb.x, 0.f) * d;
    o.y = fmaxf(acc.y * d + bb.y, 0.f) * d;
    ((float2*)g_hsB)[(size_t)warp * 32 + lane] = o;
}

// ---------------------------------------------------------------------------
// Fused layer-2 + pool: agg over hsB -> shared -> GEMM vs W2[64,128]
// (+b2, relu) -> block-granular pooled atomics into g_pool.
// 256 threads, 64 nodes/block, full W2 resident (48KB smem total).
__global__ __launch_bounds__(256) void k_fused2(const float* __restrict__ W2,
                                                const float* __restrict__ b2,
                                                const void* __restrict__ bt, int N) {
    __shared__ float xs[64 * 64];    // 16KB; reused as reduce buffer [16][128]
    __shared__ float ws[64 * 128];   // 32KB
    int t = threadIdx.x;
    int warp = t >> 5, lane = t & 31;
    int row0 = blockIdx.x * 64;

    const float4* W24 = (const float4*)W2;
    for (int i = t; i < 2048; i += 256) ((float4*)ws)[i] = W24[i];

    const float2* hs = (const float2*)g_hsB;
    for (int p = 0; p < 8; p++) {
        int r = p * 8 + warp;
        int node = row0 + r;
        float2 acc = make_float2(0.f, 0.f);
        if (node < N) {
            int s = g_rowstart[node], e = g_rowstart[node + 1];
            acc = hs[(size_t)node * 32 + lane];
            int j = s;
            for (; j + 3 < e; j += 4) {
                int s0 = g_csr[j], s1 = g_csr[j + 1], s2 = g_csr[j + 2], s3 = g_csr[j + 3];
                float2 v0 = hs[(size_t)s0 * 32 + lane];
                float2 v1 = hs[(size_t)s1 * 32 + lane];
                float2 v2 = hs[(size_t)s2 * 32 + lane];
                float2 v3 = hs[(size_t)s3 * 32 + lane];
                acc.x += (v0.x + v1.x) + (v2.x + v3.x);
                acc.y += (v0.y + v1.y) + (v2.y + v3.y);
            }
            for (; j < e; j++) {
                int s0 = g_csr[j];
                float2 v0 = hs[(size_t)s0 * 32 + lane];
                acc.x += v0.x;
                acc.y += v0.y;
            }
            float d = g_dinv[node];
            acc.x *= d; acc.y *= d;
        }
        ((float2*)xs)[r * 32 + lane] = acc;
    }
    __syncthreads();

    // GEMM: thread tile 4 rows x 8 cols over [64 x 128]
    int rg = t >> 4, cg = t & 15;
    float a[4][8] = {};
#pragma unroll
    for (int k = 0; k < 64; k += 4) {
        float4 xv[4];
#pragma unroll
        for (int i = 0; i < 4; i++)
            xv[i] = *(const float4*)&xs[(4 * rg + i) * 64 + k];
#pragma unroll
        for (int kk = 0; kk < 4; kk++) {
            float4 w0 = *(const float4*)&ws[(k + kk) * 128 + cg * 8];
            float4 w1 = *(const float4*)&ws[(k + kk) * 128 + cg * 8 + 4];
#pragma unroll
            for (int i = 0; i < 4; i++) {
                float xvv = ((const float*)&xv[i])[kk];
                a[i][0] += xvv * w0.x; a[i][1] += xvv * w0.y;
                a[i][2] += xvv * w0.z; a[i][3] += xvv * w0.w;
                a[i][4] += xvv * w1.x; a[i][5] += xvv * w1.y;
                a[i][6] += xvv * w1.z; a[i][7] += xvv * w1.w;
            }
        }
    }

    // bias + relu
    float4 bb0 = __ldg((const float4*)&b2[cg * 8]);
    float4 bb1 = __ldg((const float4*)&b2[cg * 8 + 4]);
    float bias[8] = {bb0.x, bb0.y, bb0.z, bb0.w, bb1.x, bb1.y, bb1.z, bb1.w};
#pragma unroll
    for (int i = 0; i < 4; i++)
#pragma unroll
        for (int j = 0; j < 8; j++) a[i][j] = fmaxf(a[i][j] + bias[j], 0.f);

    // pooled epilogue: fast path = whole block in one graph
    bool fast = (row0 + 64 <= N) && (load_idx(bt, row0) == load_idx(bt, row0 + 63));
    __syncthreads();   // all GEMM reads of xs complete before reuse
    if (fast) {
        float* red = xs;   // [16 rg][128 ch]
#pragma unroll
        for (int j = 0; j < 8; j++)
            red[rg * 128 + cg * 8 + j] = (a[0][j] + a[1][j]) + (a[2][j] + a[3][j]);
    }
    __syncthreads();
    if (fast) {
        if (t < 128) {
            int gid = load_idx(bt, row0);
            float s = 0.f;
#pragma unroll
            for (int r = 0; r < 16; r++) s += xs[r * 128 + t];
            atomicAdd(&g_pool[gid * 128 + t], s);
        }
    } else {
#pragma unroll
        for (int i = 0; i < 4; i++) {
            int gr = row0 + 4 * rg + i;
            if (gr < N) {
                int gid = load_idx(bt, gr);
                float* dst = &g_pool[gid * 128 + cg * 8];
#pragma unroll
                for (int j = 0; j < 8; j++) atomicAdd(&dst[j], a[i][j]);
            }
        }
    }
}

// ---------------------------------------------------------------------------
// MLP on pooled sums: one block per graph, 64 threads. Also resets grid-barrier
// counters for the next call (runs strictly after k_build in stream order).
__global__ __launch_bounds__(64) void k_poolmlp(
        const float* __restrict__ M1, const float* __restrict__ c1,
        const float* __restrict__ M2, const float* __restrict__ c2,
        const float* __restrict__ M3, const float* __restrict__ c3,
        const float* __restrict__ M4, const float* __restrict__ c4,
        float* __restrict__ out) {
    int g = blockIdx.x;
    int t = threadIdx.x;
    if (g == 0 && t == 0) {
        g_bar[0] = 0; g_bar[1] = 0; g_bar[2] = 0; g_bar[3] = 0;
    }
    __shared__ float A[128];
    __shared__ float B[64];
    __shared__ float C[64];
    __shared__ float red[64];

    float inv = 1.f / fmaxf((float)(g_off[g + 1] - g_off[g]), 1.f);
    A[t]      = g_pool[g * 128 + t] * inv;
    A[t + 64] = g_pool[g * 128 + 64 + t] * inv;
    __syncthreads();

    {
        float acc = 0.f;
#pragma unroll 4
        for (int k = 0; k < 128; k++) acc += A[k] * __ldg(&M1[k * 64 + t]);
        float v = acc + __ldg(&c1[t]);
        B[t] = (v > 0.f) ? v : 0.2f * v;
    }
    __syncthreads();
    {
        float acc = 0.f;
#pragma unroll 4
        for (int k = 0; k < 64; k++) acc += B[k] * __ldg(&M2[k * 64 + t]);
        float v = acc + __ldg(&c2[t]);
        C[t] = (v > 0.f) ? v : 0.1f * v;
    }
    __syncthreads();
    {
        float acc = 0.f;
#pragma unroll 4
        for (int k = 0; k < 64; k++) acc += C[k] * __ldg(&M3[k * 64 + t]);
        float v = acc + __ldg(&c3[t]);
        red[t] = (v > 0.f) ? v : 0.1f * v;
    }
    __syncthreads();
    {
        float p = red[t] * __ldg(&M4[t]);
        red[t] = p;
    }
    __syncthreads();
    if (t < 32) {
        float v = red[t] + red[t + 32];
#pragma unroll
        for (int o = 16; o; o >>= 1) v += __shfl_down_sync(0xffffffffu, v, o);
        if (t == 0) out[g] = fmaxf(v + __ldg(&c4[0]), 0.f);
    }
}

// ---------------------------------------------------------------------------
extern "C" void kernel_launch(void* const* d_in, const int* in_sizes, int n_in,
                              void* d_out, int out_size) {
    const float* x  = (const float*)d_in[0];
    const void*  ei = d_in[1];
    const void*  bt = d_in[2];
    const float* W1 = (const float*)d_in[3];
    const float* b1 = (const float*)d_in[4];
    const float* W2 = (const float*)d_in[5];
    const float* b2 = (const float*)d_in[6];
    const float* M1 = (const float*)d_in[7];
    const float* c1 = (const float*)d_in[8];
    const float* M2 = (const float*)d_in[9];
    const float* c2 = (const float*)d_in[10];
    const float* M3 = (const float*)d_in[11];
    const float* c3 = (const float*)d_in[12];
    const float* M4 = (const float*)d_in[13];
    const float* c4 = (const float*)d_in[14];
    float* out = (float*)d_out;

    int E = in_sizes[1] / 2;   // 800000
    int N = in_sizes[2];       // 50000

    // fork: gemm1 has no dependencies -> side stream, overlaps k_build
    cudaEventRecord(g_aux.fork, 0);
    cudaStreamWaitEvent(g_aux.s, g_aux.fork, 0);
    k_gemm1<<<(N + 63) / 64, 128, 0, g_aux.s>>>(x, W1, N);
    cudaEventRecord(g_aux.join, g_aux.s);

    // whole CSR build, one kernel
    k_build<<<NB, 256>>>(ei, bt, E, N);

    // join: agg0 needs both gemm1 (hsA) and the CSR
    cudaStreamWaitEvent(0, g_aux.join, 0);
    k_agg0<<<(N + 7) / 8, 256>>>(b1, N);
    k_fused2<<<(N + 63) / 64, 256>>>(W2, b2, bt, N);   // 4th submitted: profiled
    k_poolmlp<<<NG, 64>>>(M1, c1, M2, c2, M3, c3, M4, c4, out);
}

// round 12
// speedup vs baseline: 1.2328x; 1.2328x over previous
#include <cuda_runtime.h>
#include <math.h>

// GCNNet: 2x GCNConv(+self loops, sym norm) -> mean pool -> 4-layer MLP
// N=50000 nodes, E=800000 edges, 64 graphs, fp32 throughout.
//
//  - A(XW) == (AX)W : aggregate both layers at 64 channels.
//  - CSR: hist -> apply (scan w/ atomic block base; rows stored as int2
//    (start,end)) -> fill. g_cnt/g_total are re-zeroed by poolmlp for the
//    NEXT call (.bss zero covers the first call).
//  - gemm1 (no deps; dinv applied in agg0) overlaps the CSR build on a side
//    stream. GEMM cores use PACKED fma.rn.f32x2 (FFMA2): column pairs in
//    64-bit accumulators -> half the fma-pipe ops, bit-identical rounding.
//  - agg0 fuses layer-1 epilogue; fused2 = agg + GEMM2(+b2,relu) -> h2;
//    poolmlp = mean pool + 4-layer MLP per graph.

#define MAXN 50000
#define MAXE 800000
#define NG 64

typedef unsigned long long u64;

__device__ int   g_total;
__device__ float g_dinv[MAXN];
__device__ int   g_cnt[MAXN];
__device__ int2  g_rows[MAXN];
__device__ int   g_cursor[MAXN];
__device__ int   g_csr[MAXE];
__device__ float g_hsA[MAXN * 64];
__device__ float g_hsB[MAXN * 64];
__device__ float g_h2[(size_t)MAXN * 128];
__device__ int   g_off[NG + 1];

// ---- packed f32x2 helpers (sm_103a FFMA2 path; PTX-only) -------------------
__device__ __forceinline__ u64 pack2(float v) {
    u64 r;
    asm("mov.b64 %0, {%1, %1};" : "=l"(r) : "f"(v));
    return r;
}
__device__ __forceinline__ void ffma2(u64& d, u64 a, u64 b) {
    asm("fma.rn.f32x2 %0, %1, %2, %0;" : "+l"(d) : "l"(a), "l"(b));
}
__device__ __forceinline__ void unpack2(u64 v, float& lo, float& hi) {
    asm("mov.b64 {%0, %1}, %2;" : "=f"(lo), "=f"(hi) : "l"(v));
}

// Side stream + events (host objects, created once at load; no device allocs).
namespace {
struct Aux {
    cudaStream_t s;
    cudaEvent_t fork, join;
    Aux() {
        cudaStreamCreateWithFlags(&s, cudaStreamNonBlocking);
        cudaEventCreateWithFlags(&fork, cudaEventDisableTiming);
        cudaEventCreateWithFlags(&join, cudaEventDisableTiming);
    }
};
Aux g_aux;
}

// ---------------------------------------------------------------------------
// hist: per-block local dtype detect (edge values are random -> odd words all
// zero iff int64), then histogram of dst. g_cnt pre-zeroed by previous call.
__global__ void k_hist(const void* ei, int E) {
    __shared__ int s64;
    int t = threadIdx.x;
    if (t < 32) {
        unsigned m = __ballot_sync(0xffffffffu, ((const int*)ei)[2 * t + 1] != 0);
        if (t == 0) s64 = (m == 0u) ? 1 : 0;
    }
    __syncthreads();
    int e = blockIdx.x * 256 + t;
    if (e >= E) return;
    int d = s64 ? (int)((const long long*)ei)[(long long)E + e]
                : ((const int*)ei)[E + e];
    atomicAdd(&g_cnt[d], 1);
}

// apply: intra-block scan + atomic block base -> (start,end) per node, cursor,
// dinv, and per-graph offsets from sorted batch. bt dtype detected from the
// TAIL region (batch is sorted; head is all zeros either way).
__global__ __launch_bounds__(256) void k_apply(const void* bt, int E, int N) {
    __shared__ int s64;
    __shared__ int wt[8];
    __shared__ int wo[8];
    __shared__ int sbase;
    int t = threadIdx.x;
    int i = blockIdx.x * 256 + t;

    if (t < 32) {
        int k0 = N / 2 - 32;   // word index 2*(k0+t)+1 < N for int32 arrays
        unsigned m = __ballot_sync(0xffffffffu, ((const int*)bt)[2 * (k0 + t) + 1] != 0);
        if (t == 0) s64 = (m == 0u) ? 1 : 0;
    }
    __syncthreads();
    int is64 = s64;

    int c = (i < N) ? g_cnt[i] : 0;
    int lane = t & 31, w = t >> 5;
    int x = c;
#pragma unroll
    for (int o = 1; o < 32; o <<= 1) {
        int y = __shfl_up_sync(0xffffffffu, x, o);
        if (lane >= o) x += y;
    }
    if (lane == 31) wt[w] = x;
    __syncthreads();
    if (t < 8) {
        int s = 0;
        for (int j = 0; j < t; j++) s += wt[j];
        wo[t] = s;
    }
    if (t == 0) {
        int tot = 0;
#pragma unroll
        for (int j = 0; j < 8; j++) tot += wt[j];
        sbase = atomicAdd(&g_total, tot);
    }
    __syncthreads();

    if (i < N) {
        int start = sbase + x - c + wo[w];
        g_rows[i]   = make_int2(start, start + c);
        g_cursor[i] = start;
        g_dinv[i]   = rsqrtf((float)(c + 1));  // +1 self loop

        int bb = is64 ? (int)((const long long*)bt)[i] : ((const int*)bt)[i];
        int bp = (i == 0) ? -1
                 : (is64 ? (int)((const long long*)bt)[i - 1] : ((const int*)bt)[i - 1]);
        for (int g = bp + 1; g <= bb; g++) g_off[g] = i;
        if (i == N - 1) {
            for (int g = bb + 1; g <= NG; g++) g_off[g] = N;
        }
    }
}

__global__ void k_fill(const void* ei, int E) {
    __shared__ int s64;
    int t = threadIdx.x;
    if (t < 32) {
        unsigned m = __ballot_sync(0xffffffffu, ((const int*)ei)[2 * t + 1] != 0);
        if (t == 0) s64 = (m == 0u) ? 1 : 0;
    }
    __syncthreads();
    int e = blockIdx.x * 256 + t;
    if (e >= E) return;
    int d, s;
    if (s64) {
        d = (int)((const long long*)ei)[(long long)E + e];
        s = (int)((const long long*)ei)[e];
    } else {
        d = ((const int*)ei)[E + e];
        s = ((const int*)ei)[e];
    }
    int pos = atomicAdd(&g_cursor[d], 1);
    g_csr[pos] = s;
}

// ---------------------------------------------------------------------------
// GEMM1: hsA[r][c] = (x[r] @ W1)[c]   (UNSCALED; dinv applied in agg0)
// 128 threads, 64x64 tile, 8 rows x 4 cols per thread as 8x2 f32x2 pairs.
__global__ __launch_bounds__(128) void k_gemm1(const float* __restrict__ x,
                                               const float* __restrict__ W1, int N) {
    __shared__ float xs[64 * 64];
    __shared__ float ws[64 * 64];
    int t = threadIdx.x;
    int row0 = blockIdx.x * 64;
    int rg = t >> 4, cg = t & 15;

    u64 a2[8][2] = {};
    const float4* W14 = (const float4*)W1;
    const float4* x4  = (const float4*)x;
    float4* ws4 = (float4*)ws;
    float4* xs4 = (float4*)xs;

    for (int kh = 0; kh < 2; kh++) {
        __syncthreads();
        for (int i = t; i < 1024; i += 128) {
            int k = i >> 4, c4 = i & 15;
            ws4[i] = W14[(size_t)(kh * 64 + k) * 16 + c4];
        }
        for (int i = t; i < 1024; i += 128) {
            int r = i >> 4, kk = i & 15;
            int gr = row0 + r;
            xs4[r * 16 + kk] = (gr < N) ? x4[(size_t)gr * 32 + kh * 16 + kk]
                                        : make_float4(0.f, 0.f, 0.f, 0.f);
        }
        __syncthreads();
#pragma unroll
        for (int k = 0; k < 64; k += 4) {
            float4 xv[8];
#pragma unroll
            for (int i = 0; i < 8; i++)
                xv[i] = *(const float4*)&xs[(rg * 8 + i) * 64 + k];
#pragma unroll
            for (int kk = 0; kk < 4; kk++) {
                ulonglong2 w2 = *(const ulonglong2*)&ws[(k + kk) * 64 + cg * 4];
#pragma unroll
                for (int i = 0; i < 8; i++) {
                    u64 xx = pack2(((const float*)&xv[i])[kk]);
                    ffma2(a2[i][0], xx, w2.x);
                    ffma2(a2[i][1], xx, w2.y);
                }
            }
        }
    }
#pragma unroll
    for (int i = 0; i < 8; i++) {
        int gr = row0 + rg * 8 + i;
        if (gr < N) {
            *(ulonglong2*)&g_hsA[(size_t)gr * 64 + cg * 4] =
                make_ulonglong2(a2[i][0], a2[i][1]);
        }
    }
}

// ---------------------------------------------------------------------------
// agg0: hsB = relu( (Σ hsA[src]*dinv[src] + hsA[i]*dinv[i]) * dinv[i] + b1 ) * dinv[i]
__global__ __launch_bounds__(256) void k_agg0(const float* __restrict__ b1, int N) {
    const float2* hs = (const float2*)g_hsA;
    int warp = (blockIdx.x * blockDim.x + threadIdx.x) >> 5;
    int lane = threadIdx.x & 31;
    if (warp >= N) return;

    int2 se = g_rows[warp];
    int s = se.x, e = se.y;
    float d = g_dinv[warp];
    float2 acc = hs[(size_t)warp * 32 + lane];  // self loop
    acc.x *= d; acc.y *= d;
    int j = s;
    for (; j + 3 < e; j += 4) {
        int s0 = g_csr[j], s1 = g_csr[j + 1], s2 = g_csr[j + 2], s3 = g_csr[j + 3];
        float d0 = g_dinv[s0], d1 = g_dinv[s1], d2 = g_dinv[s2], d3 = g_dinv[s3];
        float2 v0 = hs[(size_t)s0 * 32 + lane];
        float2 v1 = hs[(size_t)s1 * 32 + lane];
        float2 v2 = hs[(size_t)s2 * 32 + lane];
        float2 v3 = hs[(size_t)s3 * 32 + lane];
        acc.x += v0.x * d0 + v1.x * d1 + v2.x * d2 + v3.x * d3;
        acc.y += v0.y * d0 + v1.y * d1 + v2.y * d2 + v3.y * d3;
    }
    for (; j < e; j++) {
        int s0 = g_csr[j];
        float d0 = g_dinv[s0];
        float2 v0 = hs[(size_t)s0 * 32 + lane];
        acc.x += v0.x * d0;
        acc.y += v0.y * d0;
    }
    float2 bb = __ldg(&((const float2*)b1)[lane]);
    float2 o;
    o.x = fmaxf(acc.x * d + bb.x, 0.f) * d;
    o.y = fmaxf(acc.y * d + bb.y, 0.f) * d;
    ((float2*)g_hsB)[(size_t)warp * 32 + lane] = o;
}

// ---------------------------------------------------------------------------
// Fused layer-2: agg over hsB -> shared -> GEMM vs W2[64,128] (+b2, relu) -> h2
// 256 threads, 64 nodes/block, full W2 resident; f32x2 GEMM core.
__global__ __launch_bounds__(256) void k_fused2(const float* __restrict__ W2,
                                                const float* __restrict__ b2, int N) {
    __shared__ float xs[64 * 64];    // 16KB
    __shared__ float ws[64 * 128];   // 32KB
    int t = threadIdx.x;
    int warp = t >> 5, lane = t & 31;
    int row0 = blockIdx.x * 64;

    const float4* W24 = (const float4*)W2;
    for (int i = t; i < 2048; i += 256) ((float4*)ws)[i] = W24[i];

    const float2* hs = (const float2*)g_hsB;
    for (int p = 0; p < 8; p++) {
        int r = p * 8 + warp;
        int node = row0 + r;
        float2 acc = make_float2(0.f, 0.f);
        if (node < N) {
            int2 se = g_rows[node];
            int s = se.x, e = se.y;
            acc = hs[(size_t)node * 32 + lane];
            int j = s;
            for (; j + 3 < e; j += 4) {
                int s0 = g_csr[j], s1 = g_csr[j + 1], s2 = g_csr[j + 2], s3 = g_csr[j + 3];
                float2 v0 = hs[(size_t)s0 * 32 + lane];
                float2 v1 = hs[(size_t)s1 * 32 + lane];
                float2 v2 = hs[(size_t)s2 * 32 + lane];
                float2 v3 = hs[(size_t)s3 * 32 + lane];
                acc.x += (v0.x + v1.x) + (v2.x + v3.x);
                acc.y += (v0.y + v1.y) + (v2.y + v3.y);
            }
            for (; j < e; j++) {
                int s0 = g_csr[j];
                float2 v0 = hs[(size_t)s0 * 32 + lane];
                acc.x += v0.x;
                acc.y += v0.y;
            }
            float d = g_dinv[node];
            acc.x *= d; acc.y *= d;
        }
        ((float2*)xs)[r * 32 + lane] = acc;
    }
    __syncthreads();

    // GEMM: 4 rows x 8 cols per thread as 4x4 f32x2 pairs
    int rg = t >> 4, cg = t & 15;
    u64 a2[4][4] = {};
#pragma unroll
    for (int k = 0; k < 64; k += 4) {
        float4 xv[4];
#pragma unroll
        for (int i = 0; i < 4; i++)
            xv[i] = *(const float4*)&xs[(4 * rg + i) * 64 + k];
#pragma unroll
        for (int kk = 0; kk < 4; kk++) {
            ulonglong2 wA = *(const ulonglong2*)&ws[(k + kk) * 128 + cg * 8];
            ulonglong2 wB = *(const ulonglong2*)&ws[(k + kk) * 128 + cg * 8 + 4];
#pragma unroll
            for (int i = 0; i < 4; i++) {
                u64 xx = pack2(((const float*)&xv[i])[kk]);
                ffma2(a2[i][0], xx, wA.x);
                ffma2(a2[i][1], xx, wA.y);
                ffma2(a2[i][2], xx, wB.x);
                ffma2(a2[i][3], xx, wB.y);
            }
        }
    }

    float4 bb0 = __ldg((const float4*)&b2[cg * 8]);
    float4 bb1 = __ldg((const float4*)&b2[cg * 8 + 4]);
    float bias[8] = {bb0.x, bb0.y, bb0.z, bb0.w, bb1.x, bb1.y, bb1.z, bb1.w};
#pragma unroll
    for (int i = 0; i < 4; i++) {
        int gr = row0 + 4 * rg + i;
        if (gr < N) {
            float v[8];
#pragma unroll
            for (int j = 0; j < 4; j++) unpack2(a2[i][j], v[2 * j], v[2 * j + 1]);
#pragma unroll
            for (int j = 0; j < 8; j++) v[j] = fmaxf(v[j] + bias[j], 0.f);
            *(float4*)&g_h2[(size_t)gr * 128 + cg * 8] =
                make_float4(v[0], v[1], v[2], v[3]);
            *(float4*)&g_h2[(size_t)gr * 128 + cg * 8 + 4] =
                make_float4(v[4], v[5], v[6], v[7]);
        }
    }
}

// ---------------------------------------------------------------------------
// Pool + MLP: one block per graph (1024 threads reduce h2, threads 0..63 run
// the MLP). Also re-zeroes g_cnt / g_total for the NEXT call.
__global__ __launch_bounds__(1024) void k_poolmlp(
        const float* __restrict__ M1, const float* __restrict__ c1,
        const float* __restrict__ M2, const float* __restrict__ c2,
        const float* __restrict__ M3, const float* __restrict__ c3,
        const float* __restrict__ M4, const float* __restrict__ c4,
        float* __restrict__ out, int N) {
    int g = blockIdx.x;
    int t = threadIdx.x;
    int c = t & 127;
    int grp = t >> 7;

    // cleanup for next call (independent of this call's outputs)
    for (int i = g * 1024 + t; i < N; i += NG * 1024) g_cnt[i] = 0;
    if (g == 0 && t == 0) g_total = 0;

    int s = g_off[g], e = g_off[g + 1];

    __shared__ float sh[1024];
    __shared__ float A[128];
    __shared__ float B[64];
    __shared__ float C[64];
    __shared__ float red[64];

    float sum = 0.f;
    for (int r = s + grp; r < e; r += 8) sum += g_h2[(size_t)r * 128 + c];
    sh[t] = sum;
    __syncthreads();
    if (grp == 0) {
        float tot = sh[c] + sh[c + 128] + sh[c + 256] + sh[c + 384] +
                    sh[c + 512] + sh[c + 640] + sh[c + 768] + sh[c + 896];
        A[c] = tot / fmaxf((float)(e - s), 1.f);
    }
    __syncthreads();

    if (t < 64) {
        float acc = 0.f;
#pragma unroll 4
        for (int k = 0; k < 128; k++) acc += A[k] * __ldg(&M1[k * 64 + t]);
        float v = acc + __ldg(&c1[t]);
        B[t] = (v > 0.f) ? v : 0.2f * v;
    }
    __syncthreads();
    if (t < 64) {
        float acc = 0.f;
#pragma unroll 4
        for (int k = 0; k < 64; k++) acc += B[k] * __ldg(&M2[k * 64 + t]);
        float v = acc + __ldg(&c2[t]);
        C[t] = (v > 0.f) ? v : 0.1f * v;
    }
    __syncthreads();
    if (t < 64) {
        float acc = 0.f;
#pragma unroll 4
        for (int k = 0; k < 64; k++) acc += C[k] * __ldg(&M3[k * 64 + t]);
        float v = acc + __ldg(&c3[t]);
        red[t] = (v > 0.f) ? v : 0.1f * v;
    }
    __syncthreads();
    if (t < 64) red[t] = red[t] * __ldg(&M4[t]);
    __syncthreads();
    if (t < 32) {
        float v = red[t] + red[t + 32];
#pragma unroll
        for (int o = 16; o; o >>= 1) v += __shfl_down_sync(0xffffffffu, v, o);
        if (t == 0) out[g] = fmaxf(v + __ldg(&c4[0]), 0.f);
    }
}

// ---------------------------------------------------------------------------
extern "C" void kernel_launch(void* const* d_in, const int* in_sizes, int n_in,
                              void* d_out, int out_size) {
    const float* x  = (const float*)d_in[0];
    const void*  ei = d_in[1];
    const void*  bt = d_in[2];
    const float* W1 = (const float*)d_in[3];
    const float* b1 = (const float*)d_in[4];
    const float* W2 = (const float*)d_in[5];
    const float* b2 = (const float*)d_in[6];
    const float* M1 = (const float*)d_in[7];
    const float* c1 = (const float*)d_in[8];
    const float* M2 = (const float*)d_in[9];
    const float* c2 = (const float*)d_in[10];
    const float* M3 = (const float*)d_in[11];
    const float* c3 = (const float*)d_in[12];
    const float* M4 = (const float*)d_in[13];
    const float* c4 = (const float*)d_in[14];
    float* out = (float*)d_out;

    int E = in_sizes[1] / 2;   // 800000
    int N = in_sizes[2];       // 50000

    // fork side stream into capture (gemm1 has no data deps)
    cudaEventRecord(g_aux.fork, 0);
    cudaStreamWaitEvent(g_aux.s, g_aux.fork, 0);

    // CSR build chain (g_cnt/g_total pre-zeroed by previous call / .bss)
    k_hist<<<(E + 255) / 256, 256>>>(ei, E);
    k_apply<<<(N + 255) / 256, 256>>>(bt, E, N);
    k_fill<<<(E + 255) / 256, 256>>>(ei, E);

    // gemm1 on side stream (4th submitted: profiled -> verifies FFMA2 gain)
    k_gemm1<<<(N + 63) / 64, 128, 0, g_aux.s>>>(x, W1, N);
    cudaEventRecord(g_aux.join, g_aux.s);
    cudaStreamWaitEvent(0, g_aux.join, 0);

    k_agg0<<<(N + 7) / 8, 256>>>(b1, N);
    k_fused2<<<(N + 63) / 64, 256>>>(W2, b2, N);
    k_poolmlp<<<NG, 1024>>>(M1, c1, M2, c2, M3, c3, M4, c4, out, N);
}